// round 1
// baseline (speedup 1.0000x reference)
#include <cuda_runtime.h>
#include <cuda_bf16.h>
#include <cstdint>

// Problem: B=32, W=256, N=512, thresholds {0.3,0.5,0.7}
// out: (B, 6) float32: [t0_b0, t0_b1, t1_b0, t1_b1, t2_b0, t2_b1] per batch row.

#define BATCH 32
#define WIN   256
#define NA    512
#define NWORDS 16   // 512 bits / 32

// ---------------- device scratch (no allocations allowed) ----------------
__device__ float g_mean[BATCH * NA];
__device__ float g_invstd[BATCH * NA];
// adjacency bitsets: [threshold][batch][row][word]
__device__ unsigned int g_adj[3][BATCH][NA][NWORDS];   // 3 MB

// ---------------- kernel 0: zero adjacency ----------------
__global__ void zero_adj_kernel() {
    unsigned int* p = &g_adj[0][0][0][0];
    int idx = blockIdx.x * blockDim.x + threadIdx.x;
    p[idx] = 0u;   // grid sized exactly
}

// ---------------- kernel 1: per-(b,n) mean & 1/(std+1e-8) ----------------
__global__ void norm_stats_kernel(const float* __restrict__ ret) {
    int n = blockIdx.x * blockDim.x + threadIdx.x;   // 0..511
    int b = blockIdx.y;
    const float* col = ret + (size_t)b * WIN * NA + n;
    float s = 0.f, s2 = 0.f;
#pragma unroll 8
    for (int w = 0; w < WIN; w++) {
        float x = col[w * NA];
        s += x;
        s2 += x * x;
    }
    float mean = s * (1.0f / WIN);
    float var = (s2 - s * mean) * (1.0f / (WIN - 1));
    var = fmaxf(var, 0.0f);
    float std = sqrtf(var);
    g_mean[b * NA + n] = mean;
    g_invstd[b * NA + n] = 1.0f / (std + 1e-8f);
}

// ---------------- kernel 2: corr tile GEMM (XᵀX/W) + threshold bitset ----------------
// grid (jb=8, ib=8, b=32), 256 threads, 64x64 C tile, 4x4 per thread, K chunks of 32.
__global__ void __launch_bounds__(256, 4)
corr_adj_kernel(const float* __restrict__ ret) {
    __shared__ float As[32][64];
    __shared__ float Bs[32][64];
    __shared__ float mi[64], si[64], mj[64], sj[64];

    const int b  = blockIdx.z;
    const int i0 = blockIdx.y * 64;
    const int j0 = blockIdx.x * 64;
    const int t  = threadIdx.x;

    if (t < 64) {
        mi[t] = g_mean[b * NA + i0 + t];
        si[t] = g_invstd[b * NA + i0 + t];
    } else if (t < 128) {
        int u = t - 64;
        mj[u] = g_mean[b * NA + j0 + u];
        sj[u] = g_invstd[b * NA + j0 + u];
    }
    __syncthreads();

    float c[4][4];
#pragma unroll
    for (int ii = 0; ii < 4; ii++)
#pragma unroll
        for (int jj = 0; jj < 4; jj++) c[ii][jj] = 0.f;

    const int ty = t >> 4;   // 0..15 -> row group
    const int tx = t & 15;   // 0..15 -> col group
    const float* base = ret + (size_t)b * WIN * NA;

    for (int wc = 0; wc < WIN; wc += 32) {
#pragma unroll
        for (int k = 0; k < 8; k++) {
            int idx = t + k * 256;
            int w = idx >> 6;        // 0..31
            int n = idx & 63;        // 0..63
            float a  = base[(size_t)(wc + w) * NA + i0 + n];
            As[w][n] = (a - mi[n]) * si[n];
            float bb = base[(size_t)(wc + w) * NA + j0 + n];
            Bs[w][n] = (bb - mj[n]) * sj[n];
        }
        __syncthreads();
#pragma unroll
        for (int kk = 0; kk < 32; kk++) {
            float4 a4 = *(const float4*)(&As[kk][ty * 4]);
            float4 b4 = *(const float4*)(&Bs[kk][tx * 4]);
            float a[4] = {a4.x, a4.y, a4.z, a4.w};
            float bb[4] = {b4.x, b4.y, b4.z, b4.w};
#pragma unroll
            for (int ii = 0; ii < 4; ii++)
#pragma unroll
                for (int jj = 0; jj < 4; jj++)
                    c[ii][jj] += a[ii] * bb[jj];
        }
        __syncthreads();
    }

    // threshold (strict >, matches reference), diag excluded, graphs are sparse
#pragma unroll
    for (int ii = 0; ii < 4; ii++) {
#pragma unroll
        for (int jj = 0; jj < 4; jj++) {
            int gi = i0 + ty * 4 + ii;
            int gj = j0 + tx * 4 + jj;
            float v = fabsf(c[ii][jj] * (1.0f / WIN));
            if (gi != gj && v > 0.3f) {
                unsigned int bit = 1u << (gj & 31);
                atomicOr(&g_adj[0][b][gi][gj >> 5], bit);
                if (v > 0.5f) {
                    atomicOr(&g_adj[1][b][gi][gj >> 5], bit);
                    if (v > 0.7f)
                        atomicOr(&g_adj[2][b][gi][gj >> 5], bit);
                }
            }
        }
    }
}

// ---------------- kernel 3: components + Betti per (threshold, batch) ----------------
// grid 96 blocks (3*32), 512 threads. Min-label propagation to unique fixed point.
__global__ void __launch_bounds__(512, 1)
betti_kernel(float* __restrict__ out) {
    __shared__ unsigned int adj[NA * NWORDS];   // 32 KB
    __shared__ int label[NA];
    __shared__ int changed;
    __shared__ int edge_cnt;
    __shared__ int comp_cnt;

    const int tt = blockIdx.x >> 5;          // threshold 0..2
    const int b  = blockIdx.x & 31;          // batch
    const int tid = threadIdx.x;

    const unsigned int* g = &g_adj[tt][b][0][0];
    for (int idx = tid; idx < NA * NWORDS; idx += NA) adj[idx] = g[idx];
    label[tid] = tid;
    if (tid == 0) { edge_cnt = 0; comp_cnt = 0; }
    __syncthreads();

    // edge count: total set bits (symmetric, zero-diag) = 2*edges
    int pc = 0;
#pragma unroll
    for (int k = 0; k < NWORDS; k++) pc += __popc(adj[tid * NWORDS + k]);
#pragma unroll
    for (int o = 16; o; o >>= 1) pc += __shfl_down_sync(0xFFFFFFFFu, pc, o);
    if ((tid & 31) == 0) atomicAdd(&edge_cnt, pc);

    // min-label propagation with pointer jumping (monotone -> unique fixed point)
    while (true) {
        __syncthreads();
        if (tid == 0) changed = 0;
        __syncthreads();
        int m = label[tid];
#pragma unroll
        for (int k = 0; k < NWORDS; k++) {
            unsigned int w = adj[tid * NWORDS + k];
            while (w) {
                int j = (k << 5) + __ffs(w) - 1;
                w &= w - 1;
                int lj = label[j];
                if (lj < m) m = lj;
            }
        }
        int lm = label[m];            // pointer jump (m is in our component)
        if (lm < m) m = lm;
        if (m < label[tid]) { label[tid] = m; changed = 1; }
        __syncthreads();
        if (!changed) break;
    }

    int isrep = (label[tid] == tid) ? 1 : 0;
#pragma unroll
    for (int o = 16; o; o >>= 1) isrep += __shfl_down_sync(0xFFFFFFFFu, isrep, o);
    if ((tid & 31) == 0) atomicAdd(&comp_cnt, isrep);
    __syncthreads();

    if (tid == 0) {
        float edges = edge_cnt * 0.5f;
        float comp = (float)comp_cnt;
        float b0 = comp;
        float b1 = fmaxf(0.0f, edges - (float)NA + comp);
        out[b * 6 + tt * 2 + 0] = b0 * (1.0f / NA);
        out[b * 6 + tt * 2 + 1] = b1 * (1.0f / NA);
    }
}

// ---------------- launch ----------------
extern "C" void kernel_launch(void* const* d_in, const int* in_sizes, int n_in,
                              void* d_out, int out_size) {
    const float* ret = (const float*)d_in[0];
    float* out = (float*)d_out;
    (void)in_sizes; (void)n_in; (void)out_size;

    // 3*32*512*16 = 786432 words
    zero_adj_kernel<<<768, 1024>>>();
    {
        dim3 g(NA / 128, BATCH);
        norm_stats_kernel<<<g, 128>>>(ret);
    }
    {
        dim3 g(NA / 64, NA / 64, BATCH);
        corr_adj_kernel<<<g, 256>>>(ret);
    }
    betti_kernel<<<96, 512>>>(out);
}

// round 2
// speedup vs baseline: 1.4309x; 1.4309x over previous
#include <cuda_runtime.h>
#include <cuda_bf16.h>
#include <cstdint>

// Problem: B=32, W=256, N=512, thresholds {0.3,0.5,0.7}
// out: (B, 6) float32: [t0_b0, t0_b1, t1_b0, t1_b1, t2_b0, t2_b1] per batch row.

#define BATCH 32
#define WIN   256
#define NA    512
#define CAP   131072   // >= max possible edges 512*511/2 = 130816

// ---------------- device scratch (no allocations allowed) ----------------
__device__ float g_mean[BATCH * NA];
__device__ float g_invstd[BATCH * NA];
__device__ int   g_ecnt[3][BATCH];               // edge counters
__device__ unsigned int g_edges[3][BATCH][CAP];  // packed (i<<16)|j, i<j  (~50MB)

// ---------------- kernel 1: per-(b,n) mean & 1/(std+1e-8); zero counters ----------------
__global__ void norm_stats_kernel(const float* __restrict__ ret) {
    int n = blockIdx.x * blockDim.x + threadIdx.x;   // 0..511
    int b = blockIdx.y;
    if (blockIdx.x == 0 && b == 0 && threadIdx.x < 96)
        ((int*)g_ecnt)[threadIdx.x] = 0;
    const float* col = ret + (size_t)b * WIN * NA + n;
    float s = 0.f, s2 = 0.f;
#pragma unroll 8
    for (int w = 0; w < WIN; w++) {
        float x = col[w * NA];
        s += x;
        s2 += x * x;
    }
    float mean = s * (1.0f / WIN);
    float var = (s2 - s * mean) * (1.0f / (WIN - 1));
    var = fmaxf(var, 0.0f);
    float std = sqrtf(var);
    g_mean[b * NA + n] = mean;
    g_invstd[b * NA + n] = 1.0f / (std + 1e-8f);
}

// ---------------- kernel 2: symmetric corr GEMM (XᵀX/W) + threshold -> edge lists ----
// 128x128 C tile, 256 threads, 8x8 per thread, K chunks of 16.
// Only upper-triangular tile pairs (10 of 16); each edge recorded once (gi<gj).
__global__ void __launch_bounds__(256, 2)
corr_adj_kernel(const float* __restrict__ ret) {
    __shared__ float As[16][128];
    __shared__ float Bs[16][128];
    __shared__ float mi[128], si[128], mj[128], sj[128];

    const int TI[10] = {0,0,0,0,1,1,1,2,2,3};
    const int TJ[10] = {0,1,2,3,1,2,3,2,3,3};

    const int b  = blockIdx.y;
    const int i0 = TI[blockIdx.x] * 128;
    const int j0 = TJ[blockIdx.x] * 128;
    const int t  = threadIdx.x;

    if (t < 128) {
        mi[t] = g_mean[b * NA + i0 + t];
        si[t] = g_invstd[b * NA + i0 + t];
    } else {
        int u = t - 128;
        mj[u] = g_mean[b * NA + j0 + u];
        sj[u] = g_invstd[b * NA + j0 + u];
    }
    __syncthreads();

    float c[8][8];
#pragma unroll
    for (int ii = 0; ii < 8; ii++)
#pragma unroll
        for (int jj = 0; jj < 8; jj++) c[ii][jj] = 0.f;

    const int ty = t >> 4;   // 0..15
    const int tx = t & 15;   // 0..15
    const float* base = ret + (size_t)b * WIN * NA;

    for (int wc = 0; wc < WIN; wc += 16) {
        // load + normalize 16x128 panels; 512 float4 per panel, 2 per thread each
#pragma unroll
        for (int k = 0; k < 2; k++) {
            int idx = t + k * 256;
            int w = idx >> 5;          // 0..15
            int n4 = idx & 31;         // float4 index within row
            int n = n4 * 4;
            float4 a = *(const float4*)(base + (size_t)(wc + w) * NA + i0 + n);
            a.x = (a.x - mi[n + 0]) * si[n + 0];
            a.y = (a.y - mi[n + 1]) * si[n + 1];
            a.z = (a.z - mi[n + 2]) * si[n + 2];
            a.w = (a.w - mi[n + 3]) * si[n + 3];
            *(float4*)(&As[w][n]) = a;
            float4 bb = *(const float4*)(base + (size_t)(wc + w) * NA + j0 + n);
            bb.x = (bb.x - mj[n + 0]) * sj[n + 0];
            bb.y = (bb.y - mj[n + 1]) * sj[n + 1];
            bb.z = (bb.z - mj[n + 2]) * sj[n + 2];
            bb.w = (bb.w - mj[n + 3]) * sj[n + 3];
            *(float4*)(&Bs[w][n]) = bb;
        }
        __syncthreads();
#pragma unroll
        for (int kk = 0; kk < 16; kk++) {
            float4 a0 = *(const float4*)(&As[kk][ty * 8]);
            float4 a1 = *(const float4*)(&As[kk][ty * 8 + 4]);
            float4 b0 = *(const float4*)(&Bs[kk][tx * 8]);
            float4 b1 = *(const float4*)(&Bs[kk][tx * 8 + 4]);
            float a[8] = {a0.x, a0.y, a0.z, a0.w, a1.x, a1.y, a1.z, a1.w};
            float bb[8] = {b0.x, b0.y, b0.z, b0.w, b1.x, b1.y, b1.z, b1.w};
#pragma unroll
            for (int ii = 0; ii < 8; ii++)
#pragma unroll
                for (int jj = 0; jj < 8; jj++)
                    c[ii][jj] += a[ii] * bb[jj];
        }
        __syncthreads();
    }

    // threshold (strict >, matches reference); record each edge once with gi<gj
#pragma unroll
    for (int ii = 0; ii < 8; ii++) {
#pragma unroll
        for (int jj = 0; jj < 8; jj++) {
            int gi = i0 + ty * 8 + ii;
            int gj = j0 + tx * 8 + jj;
            float v = fabsf(c[ii][jj] * (1.0f / WIN));
            if (gi < gj && v > 0.3f) {
                unsigned int e = ((unsigned int)gi << 16) | (unsigned int)gj;
                int p0 = atomicAdd(&g_ecnt[0][b], 1);
                g_edges[0][b][p0] = e;
                if (v > 0.5f) {
                    int p1 = atomicAdd(&g_ecnt[1][b], 1);
                    g_edges[1][b][p1] = e;
                    if (v > 0.7f) {
                        int p2 = atomicAdd(&g_ecnt[2][b], 1);
                        g_edges[2][b][p2] = e;
                    }
                }
            }
        }
    }
}

// ---------------- kernel 3: components + Betti per (threshold, batch) ----------------
// Union via min-label propagation over tiny edge lists; unique fixed point.
__global__ void __launch_bounds__(512, 1)
betti_kernel(float* __restrict__ out) {
    __shared__ int label[NA];
    __shared__ int changed;
    __shared__ int comp_cnt;

    const int tt = blockIdx.x >> 5;          // threshold 0..2
    const int b  = blockIdx.x & 31;          // batch
    const int tid = threadIdx.x;

    const int cnt = g_ecnt[tt][b];
    const unsigned int* el = &g_edges[tt][b][0];

    label[tid] = tid;
    if (tid == 0) comp_cnt = 0;

    while (true) {
        __syncthreads();
        if (tid == 0) changed = 0;
        __syncthreads();
        for (int e = tid; e < cnt; e += NA) {
            unsigned int pk = el[e];
            int i = pk >> 16, j = pk & 0xFFFF;
            int li = label[i], lj = label[j];
            if (li < lj) { atomicMin(&label[j], li); changed = 1; }
            else if (lj < li) { atomicMin(&label[i], lj); changed = 1; }
        }
        __syncthreads();
        int l = label[tid];
        int ll = label[l];                   // pointer jump
        if (ll < l) { label[tid] = ll; changed = 1; }
        __syncthreads();
        if (!changed) break;
    }

    int isrep = (label[tid] == tid) ? 1 : 0;
#pragma unroll
    for (int o = 16; o; o >>= 1) isrep += __shfl_down_sync(0xFFFFFFFFu, isrep, o);
    if ((tid & 31) == 0) atomicAdd(&comp_cnt, isrep);
    __syncthreads();

    if (tid == 0) {
        float comp = (float)comp_cnt;
        float b1 = fmaxf(0.0f, (float)cnt - (float)NA + comp);
        out[b * 6 + tt * 2 + 0] = comp * (1.0f / NA);
        out[b * 6 + tt * 2 + 1] = b1 * (1.0f / NA);
    }
}

// ---------------- launch ----------------
extern "C" void kernel_launch(void* const* d_in, const int* in_sizes, int n_in,
                              void* d_out, int out_size) {
    const float* ret = (const float*)d_in[0];
    float* out = (float*)d_out;
    (void)in_sizes; (void)n_in; (void)out_size;

    {
        dim3 g(NA / 128, BATCH);
        norm_stats_kernel<<<g, 128>>>(ret);
    }
    {
        dim3 g(10, BATCH);               // upper-triangular 128-tile pairs
        corr_adj_kernel<<<g, 256>>>(ret);
    }
    betti_kernel<<<96, 512>>>(out);
}

// round 3
// speedup vs baseline: 1.5555x; 1.0871x over previous
#include <cuda_runtime.h>
#include <cuda_bf16.h>
#include <cstdint>

// Problem: B=32, W=256, N=512, thresholds {0.3,0.5,0.7}
// out: (B, 6) float32: [t0_b0, t0_b1, t1_b0, t1_b1, t2_b0, t2_b1] per batch row.

#define BATCH 32
#define WIN   256
#define NA    512
#define CAP   131072   // >= max possible edges 512*511/2 = 130816
#define WSPL  4        // W-chunks for stats stage 1

// ---------------- device scratch (no allocations allowed) ----------------
__device__ float g_psum [WSPL][BATCH][NA];
__device__ float g_psum2[WSPL][BATCH][NA];
__device__ float g_mean[BATCH * NA];
__device__ float g_invstd[BATCH * NA];
__device__ int   g_ecnt[3][BATCH];               // edge counters
__device__ unsigned int g_edges[3][BATCH][CAP];  // packed (i<<16)|j, i<j

// packed dual-fp32 FMA: d.lo += a.lo*b.lo ; d.hi += a.hi*b.hi (exact fp32 each)
__device__ __forceinline__ void fma2(unsigned long long& d,
                                     unsigned long long a,
                                     unsigned long long b) {
    asm("fma.rn.f32x2 %0, %1, %2, %0;" : "+l"(d) : "l"(a), "l"(b));
}
__device__ __forceinline__ unsigned long long pack2(float lo, float hi) {
    unsigned long long r;
    asm("mov.b64 %0, {%1, %2};" : "=l"(r) : "f"(lo), "f"(hi));
    return r;
}

// ---------------- stats stage 1: partial sums over W chunks ----------------
__global__ void stats1_kernel(const float* __restrict__ ret) {
    int n = blockIdx.x * 128 + threadIdx.x;  // 0..511
    int b = blockIdx.y;
    int wc = blockIdx.z * (WIN / WSPL);
    const float* col = ret + (size_t)b * WIN * NA + (size_t)wc * NA + n;
    float s = 0.f, s2 = 0.f;
#pragma unroll 16
    for (int w = 0; w < WIN / WSPL; w++) {
        float x = col[(size_t)w * NA];
        s += x;
        s2 += x * x;
    }
    g_psum [blockIdx.z][b][n] = s;
    g_psum2[blockIdx.z][b][n] = s2;
}

// ---------------- stats stage 2: combine in fixed order; zero counters ------
__global__ void stats2_kernel() {
    int n = blockIdx.x * 128 + threadIdx.x;
    int b = blockIdx.y;
    if (blockIdx.x == 0 && b == 0 && threadIdx.x < 96)
        ((int*)g_ecnt)[threadIdx.x] = 0;
    float s = 0.f, s2 = 0.f;
#pragma unroll
    for (int k = 0; k < WSPL; k++) { s += g_psum[k][b][n]; s2 += g_psum2[k][b][n]; }
    float mean = s * (1.0f / WIN);
    float var = (s2 - s * mean) * (1.0f / (WIN - 1));
    var = fmaxf(var, 0.0f);
    float std = sqrtf(var);
    g_mean[b * NA + n] = mean;
    g_invstd[b * NA + n] = 1.0f / (std + 1e-8f);
}

// ---------------- corr GEMM (XᵀX/W), FFMA2, upper-tri tiles -> edge lists ----
// 128x128 C tile, 256 threads, 8x8 per thread (packed as 4x8 f32x2), K chunk 16.
__global__ void __launch_bounds__(256, 2)
corr_adj_kernel(const float* __restrict__ ret) {
    __shared__ float As[16][128];
    __shared__ float Bs[16][128];
    __shared__ float mi[128], si[128], mj[128], sj[128];

    const int TI[10] = {0,0,0,0,1,1,1,2,2,3};
    const int TJ[10] = {0,1,2,3,1,2,3,2,3,3};

    const int b  = blockIdx.y;
    const int i0 = TI[blockIdx.x] * 128;
    const int j0 = TJ[blockIdx.x] * 128;
    const int t  = threadIdx.x;

    if (t < 128) {
        mi[t] = g_mean[b * NA + i0 + t];
        si[t] = g_invstd[b * NA + i0 + t];
    } else {
        int u = t - 128;
        mj[u] = g_mean[b * NA + j0 + u];
        sj[u] = g_invstd[b * NA + j0 + u];
    }
    __syncthreads();

    // c2[ip][jj]: packed pair (ii=2*ip lo, ii=2*ip+1 hi) x jj
    unsigned long long c2[4][8];
#pragma unroll
    for (int ip = 0; ip < 4; ip++)
#pragma unroll
        for (int jj = 0; jj < 8; jj++) c2[ip][jj] = 0ull;

    const int ty = t >> 4;   // 0..15
    const int tx = t & 15;   // 0..15
    const float* base = ret + (size_t)b * WIN * NA;

    for (int wc = 0; wc < WIN; wc += 16) {
        // load + normalize 16x128 panels
#pragma unroll
        for (int k = 0; k < 2; k++) {
            int idx = t + k * 256;
            int w = idx >> 5;          // 0..15
            int n = (idx & 31) * 4;
            float4 a = *(const float4*)(base + (size_t)(wc + w) * NA + i0 + n);
            a.x = (a.x - mi[n + 0]) * si[n + 0];
            a.y = (a.y - mi[n + 1]) * si[n + 1];
            a.z = (a.z - mi[n + 2]) * si[n + 2];
            a.w = (a.w - mi[n + 3]) * si[n + 3];
            *(float4*)(&As[w][n]) = a;
            float4 bb = *(const float4*)(base + (size_t)(wc + w) * NA + j0 + n);
            bb.x = (bb.x - mj[n + 0]) * sj[n + 0];
            bb.y = (bb.y - mj[n + 1]) * sj[n + 1];
            bb.z = (bb.z - mj[n + 2]) * sj[n + 2];
            bb.w = (bb.w - mj[n + 3]) * sj[n + 3];
            *(float4*)(&Bs[w][n]) = bb;
        }
        __syncthreads();
#pragma unroll
        for (int kk = 0; kk < 16; kk++) {
            // a: natural ii-pairs straight from shared (lo = lower index)
            const unsigned long long* pa =
                (const unsigned long long*)(&As[kk][ty * 8]);
            unsigned long long ap[4];
#pragma unroll
            for (int ip = 0; ip < 4; ip++) ap[ip] = pa[ip];
            // b: broadcast packs
            float4 b0 = *(const float4*)(&Bs[kk][tx * 8]);
            float4 b1 = *(const float4*)(&Bs[kk][tx * 8 + 4]);
            unsigned long long bb[8];
            bb[0] = pack2(b0.x, b0.x); bb[1] = pack2(b0.y, b0.y);
            bb[2] = pack2(b0.z, b0.z); bb[3] = pack2(b0.w, b0.w);
            bb[4] = pack2(b1.x, b1.x); bb[5] = pack2(b1.y, b1.y);
            bb[6] = pack2(b1.z, b1.z); bb[7] = pack2(b1.w, b1.w);
#pragma unroll
            for (int ip = 0; ip < 4; ip++)
#pragma unroll
                for (int jj = 0; jj < 8; jj++)
                    fma2(c2[ip][jj], ap[ip], bb[jj]);
        }
        __syncthreads();
    }

    // threshold (strict >, matches reference); record each edge once with gi<gj
#pragma unroll
    for (int ip = 0; ip < 4; ip++) {
#pragma unroll
        for (int half = 0; half < 2; half++) {
            int ii = ip * 2 + half;
            int gi = i0 + ty * 8 + ii;
#pragma unroll
            for (int jj = 0; jj < 8; jj++) {
                unsigned int bits = half ? (unsigned int)(c2[ip][jj] >> 32)
                                         : (unsigned int)(c2[ip][jj] & 0xFFFFFFFFull);
                float cv = __uint_as_float(bits);
                int gj = j0 + tx * 8 + jj;
                float v = fabsf(cv * (1.0f / WIN));
                if (gi < gj && v > 0.3f) {
                    unsigned int e = ((unsigned int)gi << 16) | (unsigned int)gj;
                    int p0 = atomicAdd(&g_ecnt[0][b], 1);
                    g_edges[0][b][p0] = e;
                    if (v > 0.5f) {
                        int p1 = atomicAdd(&g_ecnt[1][b], 1);
                        g_edges[1][b][p1] = e;
                        if (v > 0.7f) {
                            int p2 = atomicAdd(&g_ecnt[2][b], 1);
                            g_edges[2][b][p2] = e;
                        }
                    }
                }
            }
        }
    }
}

// ---------------- components + Betti per (threshold, batch) ----------------
__global__ void __launch_bounds__(512, 1)
betti_kernel(float* __restrict__ out) {
    __shared__ int label[NA];
    __shared__ int changed;
    __shared__ int comp_cnt;

    const int tt = blockIdx.x >> 5;          // threshold 0..2
    const int b  = blockIdx.x & 31;          // batch
    const int tid = threadIdx.x;

    const int cnt = g_ecnt[tt][b];
    const unsigned int* el = &g_edges[tt][b][0];

    label[tid] = tid;
    if (tid == 0) comp_cnt = 0;

    while (true) {
        __syncthreads();
        if (tid == 0) changed = 0;
        __syncthreads();
        for (int e = tid; e < cnt; e += NA) {
            unsigned int pk = el[e];
            int i = pk >> 16, j = pk & 0xFFFF;
            int li = label[i], lj = label[j];
            if (li < lj) { atomicMin(&label[j], li); changed = 1; }
            else if (lj < li) { atomicMin(&label[i], lj); changed = 1; }
        }
        __syncthreads();
        int l = label[tid];
        int ll = label[l];                   // pointer jump
        if (ll < l) { label[tid] = ll; changed = 1; }
        __syncthreads();
        if (!changed) break;
    }

    int isrep = (label[tid] == tid) ? 1 : 0;
#pragma unroll
    for (int o = 16; o; o >>= 1) isrep += __shfl_down_sync(0xFFFFFFFFu, isrep, o);
    if ((tid & 31) == 0) atomicAdd(&comp_cnt, isrep);
    __syncthreads();

    if (tid == 0) {
        float comp = (float)comp_cnt;
        float b1 = fmaxf(0.0f, (float)cnt - (float)NA + comp);
        out[b * 6 + tt * 2 + 0] = comp * (1.0f / NA);
        out[b * 6 + tt * 2 + 1] = b1 * (1.0f / NA);
    }
}

// ---------------- launch ----------------
extern "C" void kernel_launch(void* const* d_in, const int* in_sizes, int n_in,
                              void* d_out, int out_size) {
    const float* ret = (const float*)d_in[0];
    float* out = (float*)d_out;
    (void)in_sizes; (void)n_in; (void)out_size;

    {
        dim3 g(NA / 128, BATCH, WSPL);
        stats1_kernel<<<g, 128>>>(ret);
    }
    {
        dim3 g(NA / 128, BATCH);
        stats2_kernel<<<g, 128>>>();
    }
    {
        dim3 g(10, BATCH);               // upper-triangular 128-tile pairs
        corr_adj_kernel<<<g, 256>>>(ret);
    }
    betti_kernel<<<96, 512>>>(out);
}

// round 5
// speedup vs baseline: 1.9644x; 1.2629x over previous
#include <cuda_runtime.h>
#include <cuda_bf16.h>
#include <cstdint>

// B=32, W=256, N=512, thresholds {0.3,0.5,0.7}
// out: (B,6) fp32 [t0_b0,t0_b1,t1_b0,t1_b1,t2_b0,t2_b1]

#define BATCH 32
#define WIN   256
#define NA    512
#define CAP   131072   // >= 512*511/2
#define WSPL  4
#define KCH   64       // bf16 per K-chunk (128 B rows)
#define NCH   12       // 768 / 64

// ---------------- device scratch ----------------
__device__ float g_psum [WSPL][BATCH][NA];
__device__ float g_psum2[WSPL][BATCH][NA];
__device__ float g_mean[BATCH * NA];
__device__ float g_invstd[BATCH * NA];
__device__ __nv_bfloat16 g_h[BATCH][NA][WIN];   // 8 MB
__device__ __nv_bfloat16 g_r[BATCH][NA][WIN];   // 8 MB
__device__ int   g_ecnt[3][BATCH];
__device__ unsigned int g_edges[3][BATCH][CAP];

__device__ __forceinline__ uint32_t smem_u32(const void* p) {
    uint32_t a;
    asm("{ .reg .u64 t; cvta.to.shared.u64 t, %1; cvt.u32.u64 %0, t; }" : "=r"(a) : "l"(p));
    return a;
}
#define SW128(x) ((x) ^ (((x) >> 3) & 0x70))

// ---------------- stats stage 1 ----------------
__global__ void stats1_kernel(const float* __restrict__ ret) {
    int n = blockIdx.x * 128 + threadIdx.x;
    int b = blockIdx.y;
    int wc = blockIdx.z * (WIN / WSPL);
    const float* col = ret + (size_t)b * WIN * NA + (size_t)wc * NA + n;
    float s = 0.f, s2 = 0.f;
#pragma unroll 16
    for (int w = 0; w < WIN / WSPL; w++) {
        float x = col[(size_t)w * NA];
        s += x; s2 += x * x;
    }
    g_psum [blockIdx.z][b][n] = s;
    g_psum2[blockIdx.z][b][n] = s2;
}

// ---------------- stats stage 2 (+zero edge counters) ----------------
__global__ void stats2_kernel() {
    int n = blockIdx.x * 128 + threadIdx.x;
    int b = blockIdx.y;
    if (blockIdx.x == 0 && b == 0 && threadIdx.x < 96)
        ((int*)g_ecnt)[threadIdx.x] = 0;
    float s = 0.f, s2 = 0.f;
#pragma unroll
    for (int k = 0; k < WSPL; k++) { s += g_psum[k][b][n]; s2 += g_psum2[k][b][n]; }
    float mean = s * (1.0f / WIN);
    float var = fmaxf((s2 - s * mean) * (1.0f / (WIN - 1)), 0.0f);
    g_mean[b * NA + n] = mean;
    g_invstd[b * NA + n] = 1.0f / (sqrtf(var) + 1e-8f);
}

// ---------------- convert: normalize + bf16 split + transpose ----------------
// x = h + r with h=bf16(x), r=bf16(x-h).  g_h[b][n][w], g_r[b][n][w].
__global__ void convert_kernel(const float* __restrict__ ret) {
    __shared__ float tile[32][33];
    int b = blockIdx.z, n0 = blockIdx.x * 32, w0 = blockIdx.y * 32;
    int tx = threadIdx.x, ty = threadIdx.y;   // (32,8)
#pragma unroll
    for (int rr = 0; rr < 4; rr++) {
        int wl = ty * 4 + rr;
        tile[wl][tx] = ret[((size_t)b * WIN + (w0 + wl)) * NA + n0 + tx];
    }
    __syncthreads();
#pragma unroll
    for (int rr = 0; rr < 4; rr++) {
        int nl = ty * 4 + rr;
        int n = n0 + nl, w = w0 + tx;
        float x = (tile[tx][nl] - g_mean[b * NA + n]) * g_invstd[b * NA + n];
        __nv_bfloat16 h = __float2bfloat16(x);
        __nv_bfloat16 r = __float2bfloat16(x - __bfloat162float(h));
        g_h[b][n][w] = h;
        g_r[b][n][w] = r;
    }
}

// ---------------- corr GEMM via mma.sync bf16, 3-term split ----------------
// A-role K layout: [h(0:256), r(256:512), h(512:768)]
// B-role K layout: [h(0:256), h(256:512), r(512:768)]
// A.B = h.h + r.h + h.r  (= corr - r.r, |r.r/W| ~ 2.5e-7, negligible)
__global__ void __launch_bounds__(256, 2)
corr_mma_kernel() {
    __shared__ __align__(128) __nv_bfloat16 Asm[128 * KCH];  // 16 KB
    __shared__ __align__(128) __nv_bfloat16 Bsm[128 * KCH];  // 16 KB

    const int TI[10] = {0,0,0,0,1,1,1,2,2,3};
    const int TJ[10] = {0,1,2,3,1,2,3,2,3,3};
    const int b  = blockIdx.y;
    const int i0 = TI[blockIdx.x] * 128;
    const int j0 = TJ[blockIdx.x] * 128;
    const int t = threadIdx.x;
    const int wid = t >> 5, lane = t & 31;
    const int mw = wid & 1;        // 0..1 : 64-row half
    const int nw = wid >> 1;       // 0..3 : 32-col quarter

    const uint32_t sbA = smem_u32(Asm);
    const uint32_t sbB = smem_u32(Bsm);

    float acc[4][4][4];
#pragma unroll
    for (int mt = 0; mt < 4; mt++)
#pragma unroll
        for (int nt = 0; nt < 4; nt++)
#pragma unroll
            for (int q = 0; q < 4; q++) acc[mt][nt][q] = 0.f;

    // fill indexing: thread t -> row t/2, half t&1 (64 B = 4x uint4)
    const int frow = t >> 1, fhalf = t & 1;

    for (int c = 0; c < NCH; c++) {
        const int col = (c & 3) * KCH;          // 0,64,128,192 within the 256-k source
        const __nv_bfloat16* srcA =             // A: h,h,h,h, r,r,r,r, h,h,h,h
            (c < 4 || c >= 8) ? &g_h[b][i0 + frow][col] : &g_r[b][i0 + frow][col];
        const __nv_bfloat16* srcB =             // B: h,h,h,h, h,h,h,h, r,r,r,r
            (c < 8) ? &g_h[b][j0 + frow][col] : &g_r[b][j0 + frow][col];
#pragma unroll
        for (int f = 0; f < 4; f++) {
            uint4 va = *(const uint4*)(srcA + fhalf * 32 + f * 8);
            *(uint4*)((char*)Asm + SW128(frow * 128 + fhalf * 64 + f * 16)) = va;
            uint4 vb = *(const uint4*)(srcB + fhalf * 32 + f * 8);
            *(uint4*)((char*)Bsm + SW128(frow * 128 + fhalf * 64 + f * 16)) = vb;
        }
        __syncthreads();

#pragma unroll
        for (int ks = 0; ks < 4; ks++) {        // k16 steps within chunk
            const int kb = ks * 32;             // byte offset of k16 group
            // A fragments: 4 m-tiles of 16 rows
            uint32_t af[4][4];
#pragma unroll
            for (int mt = 0; mt < 4; mt++) {
                int row = mw * 64 + mt * 16 + ((lane >> 3) & 1) * 8 + (lane & 7);
                int kbyte = kb + (lane >> 4) * 16;
                uint32_t addr = sbA + SW128(row * 128 + kbyte);
                asm volatile("ldmatrix.sync.aligned.m8n8.x4.shared.b16 {%0,%1,%2,%3}, [%4];"
                    : "=r"(af[mt][0]), "=r"(af[mt][1]), "=r"(af[mt][2]), "=r"(af[mt][3])
                    : "r"(addr));
            }
            // B fragments: 4 n-tiles of 8 rows, loaded 2 tiles per ldmatrix.x4
            uint32_t bf[4][2];
#pragma unroll
            for (int np = 0; np < 2; np++) {
                int row = nw * 32 + np * 16 + ((lane >> 4) & 1) * 8 + (lane & 7);
                int kbyte = kb + ((lane >> 3) & 1) * 16;
                uint32_t addr = sbB + SW128(row * 128 + kbyte);
                asm volatile("ldmatrix.sync.aligned.m8n8.x4.shared.b16 {%0,%1,%2,%3}, [%4];"
                    : "=r"(bf[2*np][0]), "=r"(bf[2*np][1]),
                      "=r"(bf[2*np+1][0]), "=r"(bf[2*np+1][1])
                    : "r"(addr));
            }
#pragma unroll
            for (int mt = 0; mt < 4; mt++)
#pragma unroll
                for (int nt = 0; nt < 4; nt++)
                    asm volatile(
                        "mma.sync.aligned.m16n8k16.row.col.f32.bf16.bf16.f32 "
                        "{%0,%1,%2,%3}, {%4,%5,%6,%7}, {%8,%9}, {%0,%1,%2,%3};"
                        : "+f"(acc[mt][nt][0]), "+f"(acc[mt][nt][1]),
                          "+f"(acc[mt][nt][2]), "+f"(acc[mt][nt][3])
                        : "r"(af[mt][0]), "r"(af[mt][1]), "r"(af[mt][2]), "r"(af[mt][3]),
                          "r"(bf[nt][0]), "r"(bf[nt][1]));
        }
        __syncthreads();
    }

    // epilogue: c0:(r, c) c1:(r, c+1) c2:(r+8, c) c3:(r+8, c+1)
#pragma unroll
    for (int mt = 0; mt < 4; mt++) {
#pragma unroll
        for (int nt = 0; nt < 4; nt++) {
            int gi0 = i0 + mw * 64 + mt * 16 + (lane >> 2);
            int gj0 = j0 + nw * 32 + nt * 8 + 2 * (lane & 3);
#pragma unroll
            for (int q = 0; q < 4; q++) {
                int gi = gi0 + (q >> 1) * 8;
                int gj = gj0 + (q & 1);
                float v = fabsf(acc[mt][nt][q] * (1.0f / 256.0f));
                if (gi < gj && v > 0.3f) {
                    unsigned int e = ((unsigned int)gi << 16) | (unsigned int)gj;
                    int p0 = atomicAdd(&g_ecnt[0][b], 1);
                    g_edges[0][b][p0] = e;
                    if (v > 0.5f) {
                        int p1 = atomicAdd(&g_ecnt[1][b], 1);
                        g_edges[1][b][p1] = e;
                        if (v > 0.7f) {
                            int p2 = atomicAdd(&g_ecnt[2][b], 1);
                            g_edges[2][b][p2] = e;
                        }
                    }
                }
            }
        }
    }
}

// ---------------- components + Betti ----------------
__global__ void __launch_bounds__(512, 1)
betti_kernel(float* __restrict__ out) {
    __shared__ int label[NA];
    __shared__ int changed;
    __shared__ int comp_cnt;

    const int tt = blockIdx.x >> 5;
    const int b  = blockIdx.x & 31;
    const int tid = threadIdx.x;

    const int cnt = g_ecnt[tt][b];
    const unsigned int* el = &g_edges[tt][b][0];

    label[tid] = tid;
    if (tid == 0) comp_cnt = 0;

    while (true) {
        __syncthreads();
        if (tid == 0) changed = 0;
        __syncthreads();
        for (int e = tid; e < cnt; e += NA) {
            unsigned int pk = el[e];
            int i = pk >> 16, j = pk & 0xFFFF;
            int li = label[i], lj = label[j];
            if (li < lj) { atomicMin(&label[j], li); changed = 1; }
            else if (lj < li) { atomicMin(&label[i], lj); changed = 1; }
        }
        __syncthreads();
        int l = label[tid];
        int ll = label[l];
        if (ll < l) { label[tid] = ll; changed = 1; }
        __syncthreads();
        if (!changed) break;
    }

    int isrep = (label[tid] == tid) ? 1 : 0;
#pragma unroll
    for (int o = 16; o; o >>= 1) isrep += __shfl_down_sync(0xFFFFFFFFu, isrep, o);
    if ((tid & 31) == 0) atomicAdd(&comp_cnt, isrep);
    __syncthreads();

    if (tid == 0) {
        float comp = (float)comp_cnt;
        float b1 = fmaxf(0.0f, (float)cnt - (float)NA + comp);
        out[b * 6 + tt * 2 + 0] = comp * (1.0f / NA);
        out[b * 6 + tt * 2 + 1] = b1 * (1.0f / NA);
    }
}

// ---------------- launch ----------------
extern "C" void kernel_launch(void* const* d_in, const int* in_sizes, int n_in,
                              void* d_out, int out_size) {
    const float* ret = (const float*)d_in[0];
    float* out = (float*)d_out;
    (void)in_sizes; (void)n_in; (void)out_size;

    { dim3 g(NA / 128, BATCH, WSPL); stats1_kernel<<<g, 128>>>(ret); }
    { dim3 g(NA / 128, BATCH);       stats2_kernel<<<g, 128>>>(); }
    { dim3 g(NA / 32, WIN / 32, BATCH); dim3 blk(32, 8); convert_kernel<<<g, blk>>>(ret); }
    { dim3 g(10, BATCH);             corr_mma_kernel<<<g, 256>>>(); }
    betti_kernel<<<96, 512>>>(out);
}

// round 6
// speedup vs baseline: 2.2906x; 1.1660x over previous
#include <cuda_runtime.h>
#include <cuda_bf16.h>
#include <cstdint>

// B=32, W=256, N=512, thresholds {0.3,0.5,0.7}
// out: (B,6) fp32 [t0_b0,t0_b1,t1_b0,t1_b1,t2_b0,t2_b1]

#define BATCH 32
#define WIN   256
#define NA    512
#define CAP   131072   // >= 512*511/2
#define WSPL  4
#define KCH   64       // bf16 per K-chunk (128 B rows)
#define NCH   12       // 768 / 64
#define STAGE_BYTES 32768   // 16KB A + 16KB B per stage
#define SMEM_DYN    (2 * STAGE_BYTES)

// ---------------- device scratch ----------------
__device__ float g_psum [WSPL][BATCH][NA];
__device__ float g_psum2[WSPL][BATCH][NA];
__device__ float g_mean[BATCH * NA];
__device__ float g_invstd[BATCH * NA];
__device__ __nv_bfloat16 g_h[BATCH][NA][WIN];   // 8 MB
__device__ __nv_bfloat16 g_r[BATCH][NA][WIN];   // 8 MB
__device__ int   g_ecnt[3][BATCH];
__device__ unsigned int g_edges[3][BATCH][CAP];

__device__ __forceinline__ uint32_t smem_u32(const void* p) {
    uint32_t a;
    asm("{ .reg .u64 t; cvta.to.shared.u64 t, %1; cvt.u32.u64 %0, t; }" : "=r"(a) : "l"(p));
    return a;
}
#define SW128(x) ((x) ^ (((x) >> 3) & 0x70))
#define CP16(dst, src) \
    asm volatile("cp.async.cg.shared.global [%0], [%1], 16;" :: "r"(dst), "l"(src))
#define CPCOMMIT() asm volatile("cp.async.commit_group;" ::: "memory")
#define CPWAIT1()  asm volatile("cp.async.wait_group 1;" ::: "memory")
#define CPWAIT0()  asm volatile("cp.async.wait_group 0;" ::: "memory")

// ---------------- stats stage 1 ----------------
__global__ void stats1_kernel(const float* __restrict__ ret) {
    int n = blockIdx.x * 128 + threadIdx.x;
    int b = blockIdx.y;
    int wc = blockIdx.z * (WIN / WSPL);
    const float* col = ret + (size_t)b * WIN * NA + (size_t)wc * NA + n;
    float s = 0.f, s2 = 0.f;
#pragma unroll 16
    for (int w = 0; w < WIN / WSPL; w++) {
        float x = col[(size_t)w * NA];
        s += x; s2 += x * x;
    }
    g_psum [blockIdx.z][b][n] = s;
    g_psum2[blockIdx.z][b][n] = s2;
}

// ---------------- stats stage 2 (+zero edge counters) ----------------
__global__ void stats2_kernel() {
    int n = blockIdx.x * 128 + threadIdx.x;
    int b = blockIdx.y;
    if (blockIdx.x == 0 && b == 0 && threadIdx.x < 96)
        ((int*)g_ecnt)[threadIdx.x] = 0;
    float s = 0.f, s2 = 0.f;
#pragma unroll
    for (int k = 0; k < WSPL; k++) { s += g_psum[k][b][n]; s2 += g_psum2[k][b][n]; }
    float mean = s * (1.0f / WIN);
    float var = fmaxf((s2 - s * mean) * (1.0f / (WIN - 1)), 0.0f);
    g_mean[b * NA + n] = mean;
    g_invstd[b * NA + n] = 1.0f / (sqrtf(var) + 1e-8f);
}

// ---------------- convert: normalize + bf16 split + transpose ----------------
__global__ void convert_kernel(const float* __restrict__ ret) {
    __shared__ float tile[32][33];
    int b = blockIdx.z, n0 = blockIdx.x * 32, w0 = blockIdx.y * 32;
    int tx = threadIdx.x, ty = threadIdx.y;   // (32,8)
#pragma unroll
    for (int rr = 0; rr < 4; rr++) {
        int wl = ty * 4 + rr;
        tile[wl][tx] = ret[((size_t)b * WIN + (w0 + wl)) * NA + n0 + tx];
    }
    __syncthreads();
#pragma unroll
    for (int rr = 0; rr < 4; rr++) {
        int nl = ty * 4 + rr;
        int n = n0 + nl, w = w0 + tx;
        float x = (tile[tx][nl] - g_mean[b * NA + n]) * g_invstd[b * NA + n];
        __nv_bfloat16 h = __float2bfloat16(x);
        __nv_bfloat16 r = __float2bfloat16(x - __bfloat162float(h));
        g_h[b][n][w] = h;
        g_r[b][n][w] = r;
    }
}

// ---------------- corr GEMM via mma.sync bf16, 3-term split, cp.async x2 ----
// A-role K: [h, r, h] ; B-role K: [h, h, r]  ->  A.B = h.h + r.h + h.r
__global__ void __launch_bounds__(256, 2)
corr_mma_kernel() {
    extern __shared__ __align__(128) unsigned char dsm[];
    const uint32_t sb = smem_u32(dsm);

    const int TI[10] = {0,0,0,0,1,1,1,2,2,3};
    const int TJ[10] = {0,1,2,3,1,2,3,2,3,3};
    const int b  = blockIdx.y;
    const int i0 = TI[blockIdx.x] * 128;
    const int j0 = TJ[blockIdx.x] * 128;
    const int t = threadIdx.x;
    const int wid = t >> 5, lane = t & 31;
    const int mw = wid & 1;        // 64-row half
    const int nw = wid >> 1;       // 32-col quarter

    float acc[4][4][4];
#pragma unroll
    for (int mt = 0; mt < 4; mt++)
#pragma unroll
        for (int nt = 0; nt < 4; nt++)
#pragma unroll
            for (int q = 0; q < 4; q++) acc[mt][nt][q] = 0.f;

    const int frow = t >> 1, fhalf = t & 1;
    const uint32_t fsw = SW128(frow * 128 + fhalf * 64);        // swizzle base (f*16 XOR-free within 64B)
    const __nv_bfloat16* rowAh = &g_h[b][i0 + frow][0];
    const __nv_bfloat16* rowAr = &g_r[b][i0 + frow][0];
    const __nv_bfloat16* rowBh = &g_h[b][j0 + frow][0];
    const __nv_bfloat16* rowBr = &g_r[b][j0 + frow][0];

    // loader: chunk c -> stage st
    auto load_chunk = [&](int c, int st) {
        const int col = (c & 3) * KCH + fhalf * 32;
        const __nv_bfloat16* sA = (c < 4 || c >= 8) ? rowAh + col : rowAr + col;
        const __nv_bfloat16* sB = (c < 8) ? rowBh + col : rowBr + col;
        const uint32_t base = sb + st * STAGE_BYTES;
#pragma unroll
        for (int f = 0; f < 4; f++) {
            CP16(base + (fsw ^ (f * 16)), sA + f * 8);
            CP16(base + 16384 + (fsw ^ (f * 16)), sB + f * 8);
        }
        CPCOMMIT();
    };

    load_chunk(0, 0);

    for (int c = 0; c < NCH; c++) {
        if (c + 1 < NCH) { load_chunk(c + 1, (c + 1) & 1); CPWAIT1(); }
        else             { CPWAIT0(); }
        __syncthreads();

        const uint32_t sbA = sb + (c & 1) * STAGE_BYTES;
        const uint32_t sbB = sbA + 16384;
#pragma unroll
        for (int ks = 0; ks < 4; ks++) {
            const int kb = ks * 32;
            uint32_t af[4][4];
#pragma unroll
            for (int mt = 0; mt < 4; mt++) {
                int row = mw * 64 + mt * 16 + ((lane >> 3) & 1) * 8 + (lane & 7);
                int kbyte = kb + (lane >> 4) * 16;
                uint32_t addr = sbA + SW128(row * 128 + kbyte);
                asm volatile("ldmatrix.sync.aligned.m8n8.x4.shared.b16 {%0,%1,%2,%3}, [%4];"
                    : "=r"(af[mt][0]), "=r"(af[mt][1]), "=r"(af[mt][2]), "=r"(af[mt][3])
                    : "r"(addr));
            }
            uint32_t bf[4][2];
#pragma unroll
            for (int np = 0; np < 2; np++) {
                int row = nw * 32 + np * 16 + ((lane >> 4) & 1) * 8 + (lane & 7);
                int kbyte = kb + ((lane >> 3) & 1) * 16;
                uint32_t addr = sbB + SW128(row * 128 + kbyte);
                asm volatile("ldmatrix.sync.aligned.m8n8.x4.shared.b16 {%0,%1,%2,%3}, [%4];"
                    : "=r"(bf[2*np][0]), "=r"(bf[2*np][1]),
                      "=r"(bf[2*np+1][0]), "=r"(bf[2*np+1][1])
                    : "r"(addr));
            }
#pragma unroll
            for (int mt = 0; mt < 4; mt++)
#pragma unroll
                for (int nt = 0; nt < 4; nt++)
                    asm volatile(
                        "mma.sync.aligned.m16n8k16.row.col.f32.bf16.bf16.f32 "
                        "{%0,%1,%2,%3}, {%4,%5,%6,%7}, {%8,%9}, {%0,%1,%2,%3};"
                        : "+f"(acc[mt][nt][0]), "+f"(acc[mt][nt][1]),
                          "+f"(acc[mt][nt][2]), "+f"(acc[mt][nt][3])
                        : "r"(af[mt][0]), "r"(af[mt][1]), "r"(af[mt][2]), "r"(af[mt][3]),
                          "r"(bf[nt][0]), "r"(bf[nt][1]));
        }
        __syncthreads();
    }

    // epilogue: threshold -> edge lists (gi<gj, each edge once)
#pragma unroll
    for (int mt = 0; mt < 4; mt++) {
#pragma unroll
        for (int nt = 0; nt < 4; nt++) {
            int gi0 = i0 + mw * 64 + mt * 16 + (lane >> 2);
            int gj0 = j0 + nw * 32 + nt * 8 + 2 * (lane & 3);
#pragma unroll
            for (int q = 0; q < 4; q++) {
                int gi = gi0 + (q >> 1) * 8;
                int gj = gj0 + (q & 1);
                float v = fabsf(acc[mt][nt][q] * (1.0f / 256.0f));
                if (gi < gj && v > 0.3f) {
                    unsigned int e = ((unsigned int)gi << 16) | (unsigned int)gj;
                    int p0 = atomicAdd(&g_ecnt[0][b], 1);
                    g_edges[0][b][p0] = e;
                    if (v > 0.5f) {
                        int p1 = atomicAdd(&g_ecnt[1][b], 1);
                        g_edges[1][b][p1] = e;
                        if (v > 0.7f) {
                            int p2 = atomicAdd(&g_ecnt[2][b], 1);
                            g_edges[2][b][p2] = e;
                        }
                    }
                }
            }
        }
    }
}

// ---------------- components + Betti ----------------
__global__ void __launch_bounds__(512, 1)
betti_kernel(float* __restrict__ out) {
    __shared__ int label[NA];
    __shared__ int changed;
    __shared__ int comp_cnt;

    const int tt = blockIdx.x >> 5;
    const int b  = blockIdx.x & 31;
    const int tid = threadIdx.x;

    const int cnt = g_ecnt[tt][b];
    const unsigned int* el = &g_edges[tt][b][0];

    label[tid] = tid;
    if (tid == 0) comp_cnt = 0;

    while (true) {
        __syncthreads();
        if (tid == 0) changed = 0;
        __syncthreads();
        for (int e = tid; e < cnt; e += NA) {
            unsigned int pk = el[e];
            int i = pk >> 16, j = pk & 0xFFFF;
            int li = label[i], lj = label[j];
            if (li < lj) { atomicMin(&label[j], li); changed = 1; }
            else if (lj < li) { atomicMin(&label[i], lj); changed = 1; }
        }
        __syncthreads();
        int l = label[tid];
        int ll = label[l];
        if (ll < l) { label[tid] = ll; changed = 1; }
        __syncthreads();
        if (!changed) break;
    }

    int isrep = (label[tid] == tid) ? 1 : 0;
#pragma unroll
    for (int o = 16; o; o >>= 1) isrep += __shfl_down_sync(0xFFFFFFFFu, isrep, o);
    if ((tid & 31) == 0) atomicAdd(&comp_cnt, isrep);
    __syncthreads();

    if (tid == 0) {
        float comp = (float)comp_cnt;
        float b1 = fmaxf(0.0f, (float)cnt - (float)NA + comp);
        out[b * 6 + tt * 2 + 0] = comp * (1.0f / NA);
        out[b * 6 + tt * 2 + 1] = b1 * (1.0f / NA);
    }
}

// ---------------- launch ----------------
extern "C" void kernel_launch(void* const* d_in, const int* in_sizes, int n_in,
                              void* d_out, int out_size) {
    const float* ret = (const float*)d_in[0];
    float* out = (float*)d_out;
    (void)in_sizes; (void)n_in; (void)out_size;

    static int smem_set = 0;
    if (!smem_set) {
        cudaFuncSetAttribute(corr_mma_kernel,
                             cudaFuncAttributeMaxDynamicSharedMemorySize, SMEM_DYN);
        smem_set = 1;
    }

    { dim3 g(NA / 128, BATCH, WSPL); stats1_kernel<<<g, 128>>>(ret); }
    { dim3 g(NA / 128, BATCH);       stats2_kernel<<<g, 128>>>(); }
    { dim3 g(NA / 32, WIN / 32, BATCH); dim3 blk(32, 8); convert_kernel<<<g, blk>>>(ret); }
    { dim3 g(10, BATCH);             corr_mma_kernel<<<g, 256, SMEM_DYN>>>(); }
    betti_kernel<<<96, 512>>>(out);
}

// round 7
// speedup vs baseline: 2.5498x; 1.1132x over previous
#include <cuda_runtime.h>
#include <cuda_bf16.h>
#include <cstdint>

// B=32, W=256, N=512, thresholds {0.3,0.5,0.7}
// out: (B,6) fp32 [t0_b0,t0_b1,t1_b0,t1_b1,t2_b0,t2_b1]

#define BATCH 32
#define WIN   256
#define NA    512
#define CAP   131072   // >= 512*511/2
#define WSPL  4
#define KCH   64       // bf16 per K-chunk (128 B rows)
#define NCH   12       // 768 / 64
#define NSTG  3
#define STAGE_BYTES 24576   // 16KB A(128rows) + 8KB B(64rows)
#define SMEM_DYN    (NSTG * STAGE_BYTES)
#define NTILE 20

// ---------------- device scratch ----------------
__device__ float g_psum [WSPL][BATCH][NA];
__device__ float g_psum2[WSPL][BATCH][NA];
__device__ float g_mean[BATCH * NA];
__device__ float g_invstd[BATCH * NA];
__device__ __nv_bfloat16 g_h[BATCH][NA][WIN];   // 8 MB
__device__ __nv_bfloat16 g_r[BATCH][NA][WIN];   // 8 MB
__device__ int   g_ecnt[3][BATCH];
__device__ unsigned int g_edges[3][BATCH][CAP];

__device__ __forceinline__ uint32_t smem_u32(const void* p) {
    uint32_t a;
    asm("{ .reg .u64 t; cvta.to.shared.u64 t, %1; cvt.u32.u64 %0, t; }" : "=r"(a) : "l"(p));
    return a;
}
#define SW128(x) ((x) ^ (((x) >> 3) & 0x70))
#define CP16(dst, src) \
    asm volatile("cp.async.cg.shared.global [%0], [%1], 16;" :: "r"(dst), "l"(src))
#define CPCOMMIT() asm volatile("cp.async.commit_group;" ::: "memory")
#define CPWAIT1()  asm volatile("cp.async.wait_group 1;" ::: "memory")
#define CPWAIT0()  asm volatile("cp.async.wait_group 0;" ::: "memory")

// ---------------- stats stage 1 ----------------
__global__ void stats1_kernel(const float* __restrict__ ret) {
    int n = blockIdx.x * 128 + threadIdx.x;
    int b = blockIdx.y;
    int wc = blockIdx.z * (WIN / WSPL);
    const float* col = ret + (size_t)b * WIN * NA + (size_t)wc * NA + n;
    float s = 0.f, s2 = 0.f;
#pragma unroll 16
    for (int w = 0; w < WIN / WSPL; w++) {
        float x = col[(size_t)w * NA];
        s += x; s2 += x * x;
    }
    g_psum [blockIdx.z][b][n] = s;
    g_psum2[blockIdx.z][b][n] = s2;
}

// ---------------- stats stage 2 (+zero edge counters) ----------------
__global__ void stats2_kernel() {
    int n = blockIdx.x * 128 + threadIdx.x;
    int b = blockIdx.y;
    if (blockIdx.x == 0 && b == 0 && threadIdx.x < 96)
        ((int*)g_ecnt)[threadIdx.x] = 0;
    float s = 0.f, s2 = 0.f;
#pragma unroll
    for (int k = 0; k < WSPL; k++) { s += g_psum[k][b][n]; s2 += g_psum2[k][b][n]; }
    float mean = s * (1.0f / WIN);
    float var = fmaxf((s2 - s * mean) * (1.0f / (WIN - 1)), 0.0f);
    g_mean[b * NA + n] = mean;
    g_invstd[b * NA + n] = 1.0f / (sqrtf(var) + 1e-8f);
}

// ---------------- convert: normalize + bf16 split + transpose ----------------
__global__ void convert_kernel(const float* __restrict__ ret) {
    __shared__ float tile[32][33];
    int b = blockIdx.z, n0 = blockIdx.x * 32, w0 = blockIdx.y * 32;
    int tx = threadIdx.x, ty = threadIdx.y;   // (32,8)
#pragma unroll
    for (int rr = 0; rr < 4; rr++) {
        int wl = ty * 4 + rr;
        tile[wl][tx] = ret[((size_t)b * WIN + (w0 + wl)) * NA + n0 + tx];
    }
    __syncthreads();
#pragma unroll
    for (int rr = 0; rr < 4; rr++) {
        int nl = ty * 4 + rr;
        int n = n0 + nl, w = w0 + tx;
        float x = (tile[tx][nl] - g_mean[b * NA + n]) * g_invstd[b * NA + n];
        __nv_bfloat16 h = __float2bfloat16(x);
        __nv_bfloat16 r = __float2bfloat16(x - __bfloat162float(h));
        g_h[b][n][w] = h;
        g_r[b][n][w] = r;
    }
}

// ---------------- corr GEMM: mma.sync bf16 3-term split, 3-stage cp.async ----
// A-role K: [h, r, h] ; B-role K: [h, h, r]  ->  A.B = h.h + r.h + h.r
// CTA tile 128x64, 8 warps (4x2), warp tile 32x32. Grid: 20 upper-tri tiles x 32 b.
__global__ void __launch_bounds__(256, 3)
corr_mma_kernel() {
    extern __shared__ __align__(128) unsigned char dsm[];
    const uint32_t sb = smem_u32(dsm);

    const int TI[NTILE] = {0,0,0,0,0,0,0,0, 1,1,1,1,1,1, 2,2,2,2, 3,3};
    const int TJ[NTILE] = {0,1,2,3,4,5,6,7, 2,3,4,5,6,7, 4,5,6,7, 6,7};
    const int b  = blockIdx.y;
    const int i0 = TI[blockIdx.x] * 128;
    const int j0 = TJ[blockIdx.x] * 64;
    const int t = threadIdx.x;
    const int wid = t >> 5, lane = t & 31;
    const int mw = wid >> 1;       // 0..3 : 32-row group
    const int nw = wid & 1;        // 0..1 : 32-col group

    float acc[2][4][4];
#pragma unroll
    for (int mt = 0; mt < 2; mt++)
#pragma unroll
        for (int nt = 0; nt < 4; nt++)
#pragma unroll
            for (int q = 0; q < 4; q++) acc[mt][nt][q] = 0.f;

    // A fill: thread t -> row t/2 (0..127), half t&1 (64 B = 4x16B)
    const int arow = t >> 1, ahalf = t & 1;
    const uint32_t aswz = SW128(arow * 128 + ahalf * 64);
    // B fill: thread t -> row t/4 (0..63), quarter t&3 (32 B = 2x16B)
    const int brow = t >> 2, bq = t & 3;
    const uint32_t bswz = SW128(brow * 128 + bq * 32);

    const __nv_bfloat16* rowAh = &g_h[b][i0 + arow][0];
    const __nv_bfloat16* rowAr = &g_r[b][i0 + arow][0];
    const __nv_bfloat16* rowBh = &g_h[b][j0 + brow][0];
    const __nv_bfloat16* rowBr = &g_r[b][j0 + brow][0];

    auto load_chunk = [&](int c) {
        const int st = c % NSTG;
        const uint32_t base = sb + st * STAGE_BYTES;
        const int colA = (c & 3) * KCH + ahalf * 32;
        const __nv_bfloat16* sA = (c < 4 || c >= 8) ? rowAh + colA : rowAr + colA;
#pragma unroll
        for (int f = 0; f < 4; f++)
            CP16(base + (aswz ^ (f * 16)), sA + f * 8);
        const int colB = (c & 3) * KCH + bq * 16;
        const __nv_bfloat16* sB = (c < 8) ? rowBh + colB : rowBr + colB;
        CP16(base + 16384 + bswz, sB);
        CP16(base + 16384 + (bswz ^ 16), sB + 8);
        CPCOMMIT();
    };

    load_chunk(0);
    load_chunk(1);

    for (int c = 0; c < NCH; c++) {
        if (c < NCH - 1) CPWAIT1(); else CPWAIT0();
        __syncthreads();

        const uint32_t sbA = sb + (c % NSTG) * STAGE_BYTES;
        const uint32_t sbB = sbA + 16384;
#pragma unroll
        for (int ks = 0; ks < 4; ks++) {
            const int kb = ks * 32;
            uint32_t af[2][4];
#pragma unroll
            for (int mt = 0; mt < 2; mt++) {
                int row = mw * 32 + mt * 16 + ((lane >> 3) & 1) * 8 + (lane & 7);
                int kbyte = kb + (lane >> 4) * 16;
                uint32_t addr = sbA + SW128(row * 128 + kbyte);
                asm volatile("ldmatrix.sync.aligned.m8n8.x4.shared.b16 {%0,%1,%2,%3}, [%4];"
                    : "=r"(af[mt][0]), "=r"(af[mt][1]), "=r"(af[mt][2]), "=r"(af[mt][3])
                    : "r"(addr));
            }
            uint32_t bf[4][2];
#pragma unroll
            for (int np = 0; np < 2; np++) {
                int row = nw * 32 + np * 16 + ((lane >> 4) & 1) * 8 + (lane & 7);
                int kbyte = kb + ((lane >> 3) & 1) * 16;
                uint32_t addr = sbB + SW128(row * 128 + kbyte);
                asm volatile("ldmatrix.sync.aligned.m8n8.x4.shared.b16 {%0,%1,%2,%3}, [%4];"
                    : "=r"(bf[2*np][0]), "=r"(bf[2*np][1]),
                      "=r"(bf[2*np+1][0]), "=r"(bf[2*np+1][1])
                    : "r"(addr));
            }
#pragma unroll
            for (int mt = 0; mt < 2; mt++)
#pragma unroll
                for (int nt = 0; nt < 4; nt++)
                    asm volatile(
                        "mma.sync.aligned.m16n8k16.row.col.f32.bf16.bf16.f32 "
                        "{%0,%1,%2,%3}, {%4,%5,%6,%7}, {%8,%9}, {%0,%1,%2,%3};"
                        : "+f"(acc[mt][nt][0]), "+f"(acc[mt][nt][1]),
                          "+f"(acc[mt][nt][2]), "+f"(acc[mt][nt][3])
                        : "r"(af[mt][0]), "r"(af[mt][1]), "r"(af[mt][2]), "r"(af[mt][3]),
                          "r"(bf[nt][0]), "r"(bf[nt][1]));
        }

        if (c + 2 < NCH) load_chunk(c + 2);
        else CPCOMMIT();   // keep group accounting uniform
    }

    // epilogue: threshold -> edge lists (gi<gj, each edge once)
#pragma unroll
    for (int mt = 0; mt < 2; mt++) {
#pragma unroll
        for (int nt = 0; nt < 4; nt++) {
            int gi0 = i0 + mw * 32 + mt * 16 + (lane >> 2);
            int gj0 = j0 + nw * 32 + nt * 8 + 2 * (lane & 3);
#pragma unroll
            for (int q = 0; q < 4; q++) {
                int gi = gi0 + (q >> 1) * 8;
                int gj = gj0 + (q & 1);
                float v = fabsf(acc[mt][nt][q] * (1.0f / 256.0f));
                if (gi < gj && v > 0.3f) {
                    unsigned int e = ((unsigned int)gi << 16) | (unsigned int)gj;
                    int p0 = atomicAdd(&g_ecnt[0][b], 1);
                    g_edges[0][b][p0] = e;
                    if (v > 0.5f) {
                        int p1 = atomicAdd(&g_ecnt[1][b], 1);
                        g_edges[1][b][p1] = e;
                        if (v > 0.7f) {
                            int p2 = atomicAdd(&g_ecnt[2][b], 1);
                            g_edges[2][b][p2] = e;
                        }
                    }
                }
            }
        }
    }
}

// ---------------- components + Betti ----------------
__global__ void __launch_bounds__(512, 1)
betti_kernel(float* __restrict__ out) {
    __shared__ int label[NA];
    __shared__ int changed;
    __shared__ int comp_cnt;

    const int tt = blockIdx.x >> 5;
    const int b  = blockIdx.x & 31;
    const int tid = threadIdx.x;

    const int cnt = g_ecnt[tt][b];
    const unsigned int* el = &g_edges[tt][b][0];

    label[tid] = tid;
    if (tid == 0) comp_cnt = 0;

    while (true) {
        __syncthreads();
        if (tid == 0) changed = 0;
        __syncthreads();
        for (int e = tid; e < cnt; e += NA) {
            unsigned int pk = el[e];
            int i = pk >> 16, j = pk & 0xFFFF;
            int li = label[i], lj = label[j];
            if (li < lj) { atomicMin(&label[j], li); changed = 1; }
            else if (lj < li) { atomicMin(&label[i], lj); changed = 1; }
        }
        __syncthreads();
        int l = label[tid];
        int ll = label[l];
        if (ll < l) { label[tid] = ll; changed = 1; }
        __syncthreads();
        if (!changed) break;
    }

    int isrep = (label[tid] == tid) ? 1 : 0;
#pragma unroll
    for (int o = 16; o; o >>= 1) isrep += __shfl_down_sync(0xFFFFFFFFu, isrep, o);
    if ((tid & 31) == 0) atomicAdd(&comp_cnt, isrep);
    __syncthreads();

    if (tid == 0) {
        float comp = (float)comp_cnt;
        float b1 = fmaxf(0.0f, (float)cnt - (float)NA + comp);
        out[b * 6 + tt * 2 + 0] = comp * (1.0f / NA);
        out[b * 6 + tt * 2 + 1] = b1 * (1.0f / NA);
    }
}

// ---------------- launch ----------------
extern "C" void kernel_launch(void* const* d_in, const int* in_sizes, int n_in,
                              void* d_out, int out_size) {
    const float* ret = (const float*)d_in[0];
    float* out = (float*)d_out;
    (void)in_sizes; (void)n_in; (void)out_size;

    cudaFuncSetAttribute(corr_mma_kernel,
                         cudaFuncAttributeMaxDynamicSharedMemorySize, SMEM_DYN);

    { dim3 g(NA / 128, BATCH, WSPL); stats1_kernel<<<g, 128>>>(ret); }
    { dim3 g(NA / 128, BATCH);       stats2_kernel<<<g, 128>>>(); }
    { dim3 g(NA / 32, WIN / 32, BATCH); dim3 blk(32, 8); convert_kernel<<<g, blk>>>(ret); }
    { dim3 g(NTILE, BATCH);          corr_mma_kernel<<<g, 256, SMEM_DYN>>>(); }
    betti_kernel<<<96, 512>>>(out);
}